// round 10
// baseline (speedup 1.0000x reference)
#include <cuda_runtime.h>
#include <cuda_bf16.h>
#include <cstdint>

#define B_TOT   32768
#define SAMP    16
#define D       256
#define NREL    238
#define BM      64
#define NTHREADS 256

// ---------------- device-global scratch ----------------
__device__ __align__(16) uint32_t g_Bfh[32768];   // W bf16x2 hi, mma B-fragment order
__device__ __align__(16) uint32_t g_Bfl[32768];   // W bf16x2 residual
__device__ __align__(16) float g_rwT[NREL * D];   // relation_weight transposed [r][d]
__device__ __align__(16) float g_relinit[B_TOT * D];
__device__ __align__(16) float g_agg[B_TOT * D];  // fp32 gathered means

// ---------------- smem layout for k_gemm (bytes) ----------------
#define A_PITCH  528
#define SM_AH    0
#define SM_AL    33792
#define SM_TOTAL 67584

// ---------------- helpers ----------------
__device__ __forceinline__ uint32_t smem_u32(const void* p) {
    uint32_t a;
    asm("{ .reg .u64 t; cvta.to.shared.u64 t, %1; cvt.u32.u64 %0, t; }" : "=r"(a) : "l"(p));
    return a;
}
__device__ __forceinline__ void ldsm4(uint32_t& r0, uint32_t& r1, uint32_t& r2,
                                      uint32_t& r3, uint32_t addr) {
    asm volatile("ldmatrix.sync.aligned.m8n8.x4.shared.b16 {%0,%1,%2,%3}, [%4];"
                 : "=r"(r0), "=r"(r1), "=r"(r2), "=r"(r3) : "r"(addr));
}
__device__ __forceinline__ void mma_bf16(float* c, const uint32_t* a, const uint32_t* b) {
    asm volatile("mma.sync.aligned.m16n8k16.row.col.f32.bf16.bf16.f32 "
                 "{%0,%1,%2,%3}, {%4,%5,%6,%7}, {%8,%9}, {%0,%1,%2,%3};"
                 : "+f"(c[0]), "+f"(c[1]), "+f"(c[2]), "+f"(c[3])
                 : "r"(a[0]), "r"(a[1]), "r"(a[2]), "r"(a[3]), "r"(b[0]), "r"(b[1]));
}

// ---------------- kernel 0: transpose rw + pack W fragments (proven R9) ----------------
__global__ void k_prep0(const float* __restrict__ rw, const float* __restrict__ W) {
    const int tid = threadIdx.x;
    const int bx  = blockIdx.x;

    g_rwT[bx * D + tid] = rw[tid * NREL + bx];

    if (bx < 64) {
        const int g = bx * 256 + tid;
        const int l = g & 31;
        const int j = (g >> 5) & 31;
        const int i = g >> 10;
        const int n  = j * 8 + (l >> 2);
        const int k0 = i * 16 + (l & 3) * 2;
        #pragma unroll
        for (int r = 0; r < 2; ++r) {
            const int k = k0 + r * 8;
            const float w0 = W[n * 256 + k];
            const float w1 = W[n * 256 + k + 1];
            __nv_bfloat162 h = __floats2bfloat162_rn(w0, w1);
            float2 f = __bfloat1622float2(h);
            __nv_bfloat162 lo = __floats2bfloat162_rn(w0 - f.x, w1 - f.y);
            g_Bfh[2 * g + r] = *(uint32_t*)&h;
            g_Bfl[2 * g + r] = *(uint32_t*)&lo;
        }
    }
}

// ---------------- kernel 1: merged gather (L2) + relation means (L1) ----------------
// blocks 0..511:  feature gather+mean -> g_agg (fp32), __ldcg to bypass L1
// blocks 512..1023: relation means -> g_relinit (proven R9 code, L1-resident table)
__global__ __launch_bounds__(256, 2) void k_gr(const int* __restrict__ nbr,
                                               const int* __restrict__ rel,
                                               const float* __restrict__ feat) {
    __shared__ int sIdx[1024];
    const int tid = threadIdx.x;
    const int bx  = blockIdx.x;

    if (bx < 512) {
        // ---- feature gather: rows bx*64 .. bx*64+63 ----
        const int b0 = bx * 64;
        ((int4*)sIdx)[tid] = ((const int4*)(nbr + b0 * SAMP))[tid];
        __syncthreads();

        const int q = tid & 63;                 // float4 column
        const int g = tid >> 6;                 // 0..3 (warp-uniform row group)
        const float4* F4 = (const float4*)feat;
        #pragma unroll 2
        for (int k = 0; k < 16; ++k) {
            const int row = g * 16 + k;
            const int* ids = sIdx + row * SAMP;
            float4 a = make_float4(0.f, 0.f, 0.f, 0.f);
            #pragma unroll
            for (int s = 0; s < SAMP; ++s) {
                const int n = ids[s];
                float4 v = __ldcg(&F4[n * 64 + q]);   // L2-only: keep L1 for rel blocks
                a.x += v.x; a.y += v.y; a.z += v.z; a.w += v.w;
            }
            const float inv = 1.f / 16.f;
            a.x *= inv; a.y *= inv; a.z *= inv; a.w *= inv;
            *(float4*)&g_agg[(b0 + row) * D + q * 4] = a;
        }
    } else {
        // ---- relation means: rows (bx-512)*64 .. +63 (proven R9 k_rel) ----
        const int lane = tid & 31;
        const int warp = tid >> 5;
        const int row0 = (bx - 512) * 64 + warp * 8;
        const float4* T4 = (const float4*)g_rwT;

        for (int i = 0; i < 8; ++i) {
            const int row = row0 + i;
            const int* ids = rel + row * SAMP;
            float4 lo = make_float4(0.f, 0.f, 0.f, 0.f);
            float4 hi = make_float4(0.f, 0.f, 0.f, 0.f);
            #pragma unroll
            for (int s = 0; s < SAMP; ++s) {
                const int r = __ldg(ids + s);
                float4 vl = __ldg(&T4[r * 64 + lane]);
                float4 vh = __ldg(&T4[r * 64 + 32 + lane]);
                lo.x += vl.x; lo.y += vl.y; lo.z += vl.z; lo.w += vl.w;
                hi.x += vh.x; hi.y += vh.y; hi.z += vh.z; hi.w += vh.w;
            }
            const float inv = 1.f / 16.f;
            lo.x *= inv; lo.y *= inv; lo.z *= inv; lo.w *= inv;
            hi.x *= inv; hi.y *= inv; hi.z *= inv; hi.w *= inv;
            *(float4*)&g_relinit[row * D + lane * 4]       = lo;
            *(float4*)&g_relinit[row * D + 128 + lane * 4] = hi;
        }
    }
}

// ---------------- kernel 2: stage+split agg -> mma.sync GEMM -> epilogue ----------------
__global__ __launch_bounds__(NTHREADS, 2) void k_gemm(float* __restrict__ out) {
    extern __shared__ char smem[];
    const uint32_t sbase = smem_u32(smem);
    const int tid = threadIdx.x;
    const int b0  = blockIdx.x * BM;

    // ---------- stage: read fp32 agg (coalesced), split to bf16 hi/lo padded smem ----------
    {
        const float4* src = (const float4*)(g_agg + b0 * D);   // 4096 float4s
        #pragma unroll
        for (int i = 0; i < 16; ++i) {
            const int idx = tid + i * NTHREADS;
            const int row = idx >> 6;           // 64 float4 per row
            const int seg = idx & 63;
            float4 v = src[idx];
            __nv_bfloat162 h01 = __floats2bfloat162_rn(v.x, v.y);
            __nv_bfloat162 h23 = __floats2bfloat162_rn(v.z, v.w);
            float2 f01 = __bfloat1622float2(h01);
            float2 f23 = __bfloat1622float2(h23);
            __nv_bfloat162 l01 = __floats2bfloat162_rn(v.x - f01.x, v.y - f01.y);
            __nv_bfloat162 l23 = __floats2bfloat162_rn(v.z - f23.x, v.w - f23.y);
            *(uint2*)(smem + SM_AH + row * A_PITCH + seg * 8) =
                make_uint2(*(uint32_t*)&h01, *(uint32_t*)&h23);
            *(uint2*)(smem + SM_AL + row * A_PITCH + seg * 8) =
                make_uint2(*(uint32_t*)&l01, *(uint32_t*)&l23);
        }
    }
    __syncthreads();

    // ---------- GEMM: warp tile M64xN32, B fragments via LDG.64 (proven R8/R9) ----------
    const int lane = tid & 31;
    const int warp = tid >> 5;
    const int j0   = warp * 4;

    const uint32_t aAddrH = sbase + SM_AH + (uint32_t)(lane & 15) * A_PITCH + ((lane >> 4) << 4);
    const uint32_t aAddrL = aAddrH + (SM_AL - SM_AH);

    float c[4][4][4];
    #pragma unroll
    for (int mt = 0; mt < 4; ++mt)
        #pragma unroll
        for (int nt = 0; nt < 4; ++nt)
            #pragma unroll
            for (int r = 0; r < 4; ++r) c[mt][nt][r] = 0.f;

    uint2 bh[2][4], bl[2][4];
    {
        const uint32_t base = (uint32_t)(j0 * 32 + lane) * 2;
        #pragma unroll
        for (int nt = 0; nt < 4; ++nt) {
            bh[0][nt] = *(const uint2*)(g_Bfh + base + nt * 64);
            bl[0][nt] = *(const uint2*)(g_Bfl + base + nt * 64);
        }
    }

    #pragma unroll 2
    for (int i = 0; i < 16; ++i) {
        const int cur = i & 1, nxt = cur ^ 1;
        if (i < 15) {
            const uint32_t base = (uint32_t)((i + 1) * 1024 + j0 * 32 + lane) * 2;
            #pragma unroll
            for (int nt = 0; nt < 4; ++nt) {
                bh[nxt][nt] = *(const uint2*)(g_Bfh + base + nt * 64);
                bl[nxt][nt] = *(const uint2*)(g_Bfl + base + nt * 64);
            }
        }
        #pragma unroll
        for (int mt = 0; mt < 4; ++mt) {
            uint32_t aH[4], aL[4];
            const uint32_t ao = (uint32_t)(mt * 16) * A_PITCH + (uint32_t)(i * 32);
            ldsm4(aH[0], aH[1], aH[2], aH[3], aAddrH + ao);
            ldsm4(aL[0], aL[1], aL[2], aL[3], aAddrL + ao);
            #pragma unroll
            for (int nt = 0; nt < 4; ++nt) {
                mma_bf16(c[mt][nt], aH, (const uint32_t*)&bh[cur][nt]);
                mma_bf16(c[mt][nt], aH, (const uint32_t*)&bl[cur][nt]);
                mma_bf16(c[mt][nt], aL, (const uint32_t*)&bh[cur][nt]);
            }
        }
    }

    // ---------- Epilogue: + relation mean, relu, store ----------
    {
        const int colb = warp * 32 + (lane & 3) * 2;
        const int rowb = b0 + (lane >> 2);
        #pragma unroll
        for (int mt = 0; mt < 4; ++mt) {
            const int r0 = rowb + mt * 16;
            const int r1 = r0 + 8;
            #pragma unroll
            for (int nt = 0; nt < 4; ++nt) {
                const int col = colb + nt * 8;
                float2 rv0 = *(const float2*)&g_relinit[r0 * D + col];
                float2 rv1 = *(const float2*)&g_relinit[r1 * D + col];
                float2 o0, o1;
                o0.x = fmaxf(c[mt][nt][0] + rv0.x, 0.f);
                o0.y = fmaxf(c[mt][nt][1] + rv0.y, 0.f);
                o1.x = fmaxf(c[mt][nt][2] + rv1.x, 0.f);
                o1.y = fmaxf(c[mt][nt][3] + rv1.y, 0.f);
                *(float2*)&out[r0 * D + col] = o0;
                *(float2*)&out[r1 * D + col] = o1;
            }
        }
    }
}

// ---------------- launch ----------------
extern "C" void kernel_launch(void* const* d_in, const int* in_sizes, int n_in,
                              void* d_out, int out_size) {
    (void)in_sizes; (void)n_in; (void)out_size;
    const int*   nbr  = (const int*)d_in[0];
    const int*   rel  = (const int*)d_in[1];
    const float* feat = (const float*)d_in[2];
    const float* W    = (const float*)d_in[3];
    const float* rw   = (const float*)d_in[4];
    float* out = (float*)d_out;

    cudaFuncSetAttribute(k_gemm, cudaFuncAttributeMaxDynamicSharedMemorySize, SM_TOTAL);

    k_prep0<<<NREL, 256>>>(rw, W);
    k_gr<<<1024, 256>>>(nbr, rel, feat);
    k_gemm<<<B_TOT / BM, NTHREADS, SM_TOTAL>>>(out);
}

// round 11
// speedup vs baseline: 1.2040x; 1.2040x over previous
#include <cuda_runtime.h>
#include <cuda_bf16.h>
#include <cstdint>

#define B_TOT   32768
#define SAMP    16
#define D       256
#define NREL    238
#define BM      64
#define NTHREADS 256

// ---------------- device-global scratch ----------------
__device__ __align__(16) uint32_t g_Bfh[32768];   // W bf16x2 hi, mma B-fragment order
__device__ __align__(16) uint32_t g_Bfl[32768];   // W bf16x2 residual
__device__ __align__(16) float g_rwT[NREL * D];   // relation_weight transposed [r][d]

// ---------------- smem layout for k_main (bytes) ----------------
#define SM_IDX   0              // 1024 ints
#define SM_AH    4096           // 64 * 528
#define SM_AL    37888
#define SM_REL   4096           // overlays AH/AL after GEMM: 64 rows * 1056 B
#define SM_TOTAL 71680
#define A_PITCH  528
#define REL_PITCH_B 1056        // 264 floats

// ---------------- helpers ----------------
__device__ __forceinline__ uint32_t smem_u32(const void* p) {
    uint32_t a;
    asm("{ .reg .u64 t; cvta.to.shared.u64 t, %1; cvt.u32.u64 %0, t; }" : "=r"(a) : "l"(p));
    return a;
}
__device__ __forceinline__ void ldsm4(uint32_t& r0, uint32_t& r1, uint32_t& r2,
                                      uint32_t& r3, uint32_t addr) {
    asm volatile("ldmatrix.sync.aligned.m8n8.x4.shared.b16 {%0,%1,%2,%3}, [%4];"
                 : "=r"(r0), "=r"(r1), "=r"(r2), "=r"(r3) : "r"(addr));
}
__device__ __forceinline__ void mma_bf16(float* c, const uint32_t* a, const uint32_t* b) {
    asm volatile("mma.sync.aligned.m16n8k16.row.col.f32.bf16.bf16.f32 "
                 "{%0,%1,%2,%3}, {%4,%5,%6,%7}, {%8,%9}, {%0,%1,%2,%3};"
                 : "+f"(c[0]), "+f"(c[1]), "+f"(c[2]), "+f"(c[3])
                 : "r"(a[0]), "r"(a[1]), "r"(a[2]), "r"(a[3]), "r"(b[0]), "r"(b[1]));
}

// ---------------- kernel 0: transpose rw + pack W fragments (proven R9) ----------------
__global__ void k_prep0(const float* __restrict__ rw, const float* __restrict__ W) {
    const int tid = threadIdx.x;
    const int bx  = blockIdx.x;

    g_rwT[bx * D + tid] = rw[tid * NREL + bx];

    if (bx < 64) {
        const int g = bx * 256 + tid;
        const int l = g & 31;
        const int j = (g >> 5) & 31;
        const int i = g >> 10;
        const int n  = j * 8 + (l >> 2);
        const int k0 = i * 16 + (l & 3) * 2;
        #pragma unroll
        for (int r = 0; r < 2; ++r) {
            const int k = k0 + r * 8;
            const float w0 = W[n * 256 + k];
            const float w1 = W[n * 256 + k + 1];
            __nv_bfloat162 h = __floats2bfloat162_rn(w0, w1);
            float2 f = __bfloat1622float2(h);
            __nv_bfloat162 lo = __floats2bfloat162_rn(w0 - f.x, w1 - f.y);
            g_Bfh[2 * g + r] = *(uint32_t*)&h;
            g_Bfl[2 * g + r] = *(uint32_t*)&lo;
        }
    }
}

// ---------------- kernel 1: gather+mean -> split -> GEMM -> rel gather -> epilogue ----
__global__ __launch_bounds__(NTHREADS, 2) void k_main(const int* __restrict__ nbr,
                                                      const int* __restrict__ rel,
                                                      const float* __restrict__ feat,
                                                      float* __restrict__ out) {
    extern __shared__ char smem[];
    const uint32_t sbase = smem_u32(smem);
    const int tid = threadIdx.x;
    const int b0  = blockIdx.x * BM;

    ((int4*)(smem + SM_IDX))[tid] = ((const int4*)(nbr + b0 * SAMP))[tid];
    __syncthreads();

    // ---------- Phase A: gather + mean (L2-only loads), split bf16 hi/lo to smem ----------
    {
        const int q = tid & 63;
        const int g = tid >> 6;
        const float4* F4 = (const float4*)feat;
        const int* sIdx = (const int*)(smem + SM_IDX);
        #pragma unroll 2
        for (int k = 0; k < 16; ++k) {
            const int row = g * 16 + k;
            const int* ids = sIdx + row * SAMP;
            float4 a = make_float4(0.f, 0.f, 0.f, 0.f);
            #pragma unroll
            for (int s = 0; s < SAMP; ++s) {
                const int n = ids[s];
                float4 v = __ldcg(&F4[n * 64 + q]);   // L2-only: keep L1 for rel table
                a.x += v.x; a.y += v.y; a.z += v.z; a.w += v.w;
            }
            const float inv = 1.f / 16.f;
            a.x *= inv; a.y *= inv; a.z *= inv; a.w *= inv;
            __nv_bfloat162 h01 = __floats2bfloat162_rn(a.x, a.y);
            __nv_bfloat162 h23 = __floats2bfloat162_rn(a.z, a.w);
            float2 f01 = __bfloat1622float2(h01);
            float2 f23 = __bfloat1622float2(h23);
            __nv_bfloat162 l01 = __floats2bfloat162_rn(a.x - f01.x, a.y - f01.y);
            __nv_bfloat162 l23 = __floats2bfloat162_rn(a.z - f23.x, a.w - f23.y);
            *(uint2*)(smem + SM_AH + row * A_PITCH + q * 8) =
                make_uint2(*(uint32_t*)&h01, *(uint32_t*)&h23);
            *(uint2*)(smem + SM_AL + row * A_PITCH + q * 8) =
                make_uint2(*(uint32_t*)&l01, *(uint32_t*)&l23);
        }
    }
    __syncthreads();

    // ---------- Phase B: GEMM warp tile M64xN32, B fragments via LDG.64 (proven) ----------
    const int lane = tid & 31;
    const int warp = tid >> 5;
    const int j0   = warp * 4;

    const uint32_t aAddrH = sbase + SM_AH + (uint32_t)(lane & 15) * A_PITCH + ((lane >> 4) << 4);
    const uint32_t aAddrL = aAddrH + (SM_AL - SM_AH);

    float c[4][4][4];
    #pragma unroll
    for (int mt = 0; mt < 4; ++mt)
        #pragma unroll
        for (int nt = 0; nt < 4; ++nt)
            #pragma unroll
            for (int r = 0; r < 4; ++r) c[mt][nt][r] = 0.f;

    uint2 bh[2][4], bl[2][4];
    {
        const uint32_t base = (uint32_t)(j0 * 32 + lane) * 2;
        #pragma unroll
        for (int nt = 0; nt < 4; ++nt) {
            bh[0][nt] = *(const uint2*)(g_Bfh + base + nt * 64);
            bl[0][nt] = *(const uint2*)(g_Bfl + base + nt * 64);
        }
    }

    #pragma unroll 2
    for (int i = 0; i < 16; ++i) {
        const int cur = i & 1, nxt = cur ^ 1;
        if (i < 15) {
            const uint32_t base = (uint32_t)((i + 1) * 1024 + j0 * 32 + lane) * 2;
            #pragma unroll
            for (int nt = 0; nt < 4; ++nt) {
                bh[nxt][nt] = *(const uint2*)(g_Bfh + base + nt * 64);
                bl[nxt][nt] = *(const uint2*)(g_Bfl + base + nt * 64);
            }
        }
        #pragma unroll
        for (int mt = 0; mt < 4; ++mt) {
            uint32_t aH[4], aL[4];
            const uint32_t ao = (uint32_t)(mt * 16) * A_PITCH + (uint32_t)(i * 32);
            ldsm4(aH[0], aH[1], aH[2], aH[3], aAddrH + ao);
            ldsm4(aL[0], aL[1], aL[2], aL[3], aAddrL + ao);
            #pragma unroll
            for (int nt = 0; nt < 4; ++nt) {
                mma_bf16(c[mt][nt], aH, (const uint32_t*)&bh[cur][nt]);
                mma_bf16(c[mt][nt], aH, (const uint32_t*)&bl[cur][nt]);
                mma_bf16(c[mt][nt], aL, (const uint32_t*)&bh[cur][nt]);
            }
        }
    }
    __syncthreads();                            // A tiles dead; rel overlays them

    // ---------- Phase C: relation means into smem (L1-resident table) ----------
    {
        const float4* T4 = (const float4*)g_rwT;    // [238][64] float4
        for (int i = 0; i < 8; ++i) {
            const int row = warp * 8 + i;
            const int* ids = rel + (b0 + row) * SAMP;
            float4 lo = make_float4(0.f, 0.f, 0.f, 0.f);
            float4 hi = make_float4(0.f, 0.f, 0.f, 0.f);
            #pragma unroll
            for (int s = 0; s < SAMP; ++s) {
                const int r = __ldg(ids + s);       // warp-uniform broadcast
                float4 vl = __ldg(&T4[r * 64 + lane]);
                float4 vh = __ldg(&T4[r * 64 + 32 + lane]);
                lo.x += vl.x; lo.y += vl.y; lo.z += vl.z; lo.w += vl.w;
                hi.x += vh.x; hi.y += vh.y; hi.z += vh.z; hi.w += vh.w;
            }
            const float inv = 1.f / 16.f;
            lo.x *= inv; lo.y *= inv; lo.z *= inv; lo.w *= inv;
            hi.x *= inv; hi.y *= inv; hi.z *= inv; hi.w *= inv;
            *(float4*)(smem + SM_REL + row * REL_PITCH_B + lane * 16)       = lo;
            *(float4*)(smem + SM_REL + row * REL_PITCH_B + 512 + lane * 16) = hi;
        }
    }
    __syncthreads();

    // ---------- Epilogue: + relation mean (smem), relu, streaming store ----------
    {
        const int colb = warp * 32 + (lane & 3) * 2;
        const int rowl = lane >> 2;                 // local row base
        #pragma unroll
        for (int mt = 0; mt < 4; ++mt) {
            const int r0l = rowl + mt * 16;
            const int r1l = r0l + 8;
            #pragma unroll
            for (int nt = 0; nt < 4; ++nt) {
                const int col = colb + nt * 8;
                float2 rv0 = *(const float2*)(smem + SM_REL + r0l * REL_PITCH_B + col * 4);
                float2 rv1 = *(const float2*)(smem + SM_REL + r1l * REL_PITCH_B + col * 4);
                float2 o0, o1;
                o0.x = fmaxf(c[mt][nt][0] + rv0.x, 0.f);
                o0.y = fmaxf(c[mt][nt][1] + rv0.y, 0.f);
                o1.x = fmaxf(c[mt][nt][2] + rv1.x, 0.f);
                o1.y = fmaxf(c[mt][nt][3] + rv1.y, 0.f);
                __stcs((float2*)&out[(b0 + r0l) * D + col], o0);
                __stcs((float2*)&out[(b0 + r1l) * D + col], o1);
            }
        }
    }
}

// ---------------- launch ----------------
extern "C" void kernel_launch(void* const* d_in, const int* in_sizes, int n_in,
                              void* d_out, int out_size) {
    (void)in_sizes; (void)n_in; (void)out_size;
    const int*   nbr  = (const int*)d_in[0];
    const int*   rel  = (const int*)d_in[1];
    const float* feat = (const float*)d_in[2];
    const float* W    = (const float*)d_in[3];
    const float* rw   = (const float*)d_in[4];
    float* out = (float*)d_out;

    cudaFuncSetAttribute(k_main, cudaFuncAttributeMaxDynamicSharedMemorySize, SM_TOTAL);

    k_prep0<<<NREL, 256>>>(rw, W);
    k_main<<<B_TOT / BM, NTHREADS, SM_TOTAL>>>(nbr, rel, feat, out);
}